// round 6
// baseline (speedup 1.0000x reference)
#include <cuda_runtime.h>
#include <math.h>

#define LMAX 20
#define NK   210           // LMAX*(LMAX+1)/2
#define NCOL 400
#define T    256           // threads/block
#define PTS  128           // points/block (2 threads per point)
#define STRIDE 101         // smem row stride in floats (odd -> conflict-free STS)
#define NM   10            // m values per parity-thread

__device__ float2 g_AB[NK];     // normalized recurrence coeffs A,B per (l,m)
__device__ float  g_D2[LMAX];   // skip-2 sectoral diagonal coeff per l
__device__ float  g_S[2];       // seeds: Pbar(0,0), and -norm(1,1) (x sx)

// Tables in double precision. Pbar(l,m) = K(l,m)*P(l,m) (Condon-Shortley in P).
// Pbar(l,m) = A(l,m)*x*Pbar(l-1,m) - B(l,m)*Pbar(l-2,m)
//   A = sqrt((2l-1)(2l+1)/((l-m)(l+m))),  B = (l+m-1)/(l-m)*sqrt(r2), B=0 at l=m+1
// Pbar(m,m) = D2(m)*sx^2*Pbar(m-2,m-2)
__global__ void init_tables() {
    int idx = threadIdx.x;
    if (idx < NK) {
        int l = 0;
        while ((l + 1) * (l + 2) / 2 <= idx) ++l;
        int m = idx - l * (l + 1) / 2;
        double A = 0.0, Bc = 0.0;
        if (l >= m + 1) {
            A = sqrt((double)((2 * l + 1) * (2 * l - 1)) /
                     (double)((l - m) * (l + m)));
            if (l >= m + 2) {
                double r = (double)(2 * l + 1) / (double)(2 * l - 3)
                         * (double)((l - m) * (l - m - 1))
                         / (double)((l + m) * (l + m - 1));
                Bc = (double)(l + m - 1) / (double)(l - m) * sqrt(r);
            }
        }
        g_AB[idx] = make_float2((float)A, (float)Bc);
    }
    if (idx >= 2 && idx < LMAX) {
        int m = idx;
        double r = (double)(2 * m + 1) / (double)(2 * m - 3);
        r /= (double)(2 * m) * (2 * m - 1) * (2 * m - 2) * (2 * m - 3);
        g_D2[m] = (float)((double)((2 * m - 1) * (2 * m - 3)) * sqrt(r));
    }
    if (idx == 0) {
        g_S[0] = (float)sqrt(1.0 / (4.0 * 3.14159265358979323846));
        g_S[1] = (float)(-sqrt(3.0 / (8.0 * 3.14159265358979323846)));
    }
}

// Rows l in [L0,L1); this thread handles m = PAR, PAR+2, ... Emits cols - CBASE.
template<int L0, int L1, int CBASE, int PAR>
__device__ __forceinline__ void compute_rows(
    float* __restrict__ row, const float2* __restrict__ sAB,
    const float* __restrict__ sD2,
    float x, float sx2, float seed,
    const float (&CM)[NM], const float (&SM)[NM],
    float (&Pa)[NM], float (&Pb)[NM])
{
    #pragma unroll
    for (int l = L0; l < L1; ++l) {
        float Pn[NM];
        #pragma unroll
        for (int j = 0; j < NM; ++j) {
            const int m = PAR + 2 * j;
            if (m > l) continue;
            if (m == l) {
                Pn[j] = (j == 0) ? seed : sD2[l] * sx2 * Pb[j - 1];
            } else {
                float2 ab = sAB[l * (l + 1) / 2 + m];   // LDS.64 broadcast
                Pn[j] = fmaf(ab.x * x, Pa[j], -(ab.y * Pb[j]));
            }
        }
        const int base = l * l + l - CBASE;
        #pragma unroll
        for (int j = 0; j < NM; ++j) {
            const int m = PAR + 2 * j;
            if (m > l) continue;
            float t = Pn[j];
            if (m == 0) row[base] = t;
            else { row[base + m] = t * CM[j]; row[base - m] = t * SM[j]; }
        }
        #pragma unroll
        for (int j = 0; j < NM; ++j) {
            const int m = PAR + 2 * j;
            if (m > l) continue;
            Pb[j] = Pa[j]; Pa[j] = Pn[j];
        }
    }
}

// Coalesced, conflict-free scalar copy: col fastest -> 32 lanes read 32
// consecutive floats of one smem row (stride 101 => 32 distinct banks) and
// store one contiguous 128B gmem line.
template<int CBASE, int COLS>
__device__ __forceinline__ void writeback(
    const float* __restrict__ sh, float* __restrict__ out,
    int p0, int np, int tid)
{
    int total = np * COLS;
    for (int j = tid; j < total; j += T) {
        int r = j / COLS;            // constexpr divisor -> mul/shift
        int k = j - r * COLS;
        out[(size_t)(p0 + r) * NCOL + CBASE + k] = sh[r * STRIDE + k];
    }
}

__global__ __launch_bounds__(T, 3) void sh_kernel(
    const float* __restrict__ lonlat, float* __restrict__ out, int B)
{
    __shared__ float2 sAB[NK];
    __shared__ float  sD2[LMAX];
    __shared__ float  sS[2];
    extern __shared__ float sh[];

    const int tid = threadIdx.x;
    const int pt  = tid & (PTS - 1);
    const int par = tid >> 7;               // 0: even m, 1: odd m
    const int p0  = blockIdx.x * PTS;
    const int np  = min(PTS, B - p0);

    for (int i = tid; i < NK; i += T) sAB[i] = g_AB[i];
    if (tid < LMAX) sD2[tid] = g_D2[tid];
    if (tid < 2)    sS[tid]  = g_S[tid];
    __syncthreads();

    const bool active = (pt < np);
    float x = 0.f, sx2 = 0.f, seed = 0.f;
    float CM[NM], SM[NM], Pa[NM], Pb[NM];

    if (active) {
        float2 ll = reinterpret_cast<const float2*>(lonlat)[p0 + pt];
        const float d2r = 0.017453292519943295f;
        float phi   = (ll.x + 180.0f) * d2r;
        float theta = (ll.y +  90.0f) * d2r;
        x = cosf(theta);
        float sx = sinf(theta);
        sx2 = sx * sx;
        float s1, c1;
        sincosf(phi, &s1, &c1);
        float c2 = c1 * c1 - s1 * s1;       // cos(2phi)
        float s2 = 2.0f * s1 * c1;          // sin(2phi)
        const float SQ2 = 1.41421356237309505f;
        if (par == 0) { CM[0] = SQ2;      SM[0] = 0.0f;
                        seed = sS[0]; }
        else          { CM[0] = SQ2 * c1; SM[0] = SQ2 * s1;
                        seed = sS[1] * sx; }
        #pragma unroll
        for (int j = 1; j < NM; ++j) {
            CM[j] = CM[j - 1] * c2 - SM[j - 1] * s2;
            SM[j] = SM[j - 1] * c2 + CM[j - 1] * s2;
        }
        #pragma unroll
        for (int j = 0; j < NM; ++j) { Pa[j] = 0.0f; Pb[j] = 0.0f; }
    }

    float* row = sh + pt * STRIDE;

    // chunk 0: l 0..9   cols [0,100)
    if (active) {
        if (par == 0) compute_rows<0, 10, 0, 0>(row, sAB, sD2, x, sx2, seed, CM, SM, Pa, Pb);
        else          compute_rows<0, 10, 0, 1>(row, sAB, sD2, x, sx2, seed, CM, SM, Pa, Pb);
    }
    __syncthreads();
    writeback<0, 100>(sh, out, p0, np, tid);
    __syncthreads();

    // chunk 1: l 10..13 cols [100,196)
    if (active) {
        if (par == 0) compute_rows<10, 14, 100, 0>(row, sAB, sD2, x, sx2, seed, CM, SM, Pa, Pb);
        else          compute_rows<10, 14, 100, 1>(row, sAB, sD2, x, sx2, seed, CM, SM, Pa, Pb);
    }
    __syncthreads();
    writeback<100, 96>(sh, out, p0, np, tid);
    __syncthreads();

    // chunk 2: l 14..15 cols [196,256)
    if (active) {
        if (par == 0) compute_rows<14, 16, 196, 0>(row, sAB, sD2, x, sx2, seed, CM, SM, Pa, Pb);
        else          compute_rows<14, 16, 196, 1>(row, sAB, sD2, x, sx2, seed, CM, SM, Pa, Pb);
    }
    __syncthreads();
    writeback<196, 60>(sh, out, p0, np, tid);
    __syncthreads();

    // chunk 3: l 16..17 cols [256,324)
    if (active) {
        if (par == 0) compute_rows<16, 18, 256, 0>(row, sAB, sD2, x, sx2, seed, CM, SM, Pa, Pb);
        else          compute_rows<16, 18, 256, 1>(row, sAB, sD2, x, sx2, seed, CM, SM, Pa, Pb);
    }
    __syncthreads();
    writeback<256, 68>(sh, out, p0, np, tid);
    __syncthreads();

    // chunk 4: l 18..19 cols [324,400)
    if (active) {
        if (par == 0) compute_rows<18, 20, 324, 0>(row, sAB, sD2, x, sx2, seed, CM, SM, Pa, Pb);
        else          compute_rows<18, 20, 324, 1>(row, sAB, sD2, x, sx2, seed, CM, SM, Pa, Pb);
    }
    __syncthreads();
    writeback<324, 76>(sh, out, p0, np, tid);
}

extern "C" void kernel_launch(void* const* d_in, const int* in_sizes, int n_in,
                              void* d_out, int out_size)
{
    const float* lonlat = (const float*)d_in[0];
    float* out = (float*)d_out;
    int B = in_sizes[0] / 2;

    size_t smem = (size_t)PTS * STRIDE * sizeof(float);   // 51,712 B dynamic
    cudaFuncSetAttribute(sh_kernel,
                         cudaFuncAttributeMaxDynamicSharedMemorySize, (int)smem);

    init_tables<<<1, 256>>>();
    int grid = (B + PTS - 1) / PTS;
    sh_kernel<<<grid, T, smem>>>(lonlat, out, B);
}

// round 7
// speedup vs baseline: 1.0042x; 1.0042x over previous
#include <cuda_runtime.h>
#include <math.h>

#define LMAX 20
#define NK   210           // LMAX*(LMAX+1)/2
#define NCOL 400
#define T    256           // threads/block
#define PTS  128           // points/block (2 threads per point)
#define STRIDE 101         // smem row stride in floats (odd -> conflict-free STS)
#define NM   10            // m values per parity-thread

__device__ float2 g_AB[NK];     // normalized recurrence coeffs A,B per (l,m)
__device__ float  g_D2[LMAX];   // skip-2 sectoral diagonal coeff per l
__device__ float  g_S[2];       // seeds: Pbar(0,0), and -norm(1,1) (x sx)

// Tables in double precision. Pbar(l,m) = K(l,m)*P(l,m) (Condon-Shortley in P).
// Pbar(l,m) = A(l,m)*x*Pbar(l-1,m) - B(l,m)*Pbar(l-2,m)
//   A = sqrt((2l-1)(2l+1)/((l-m)(l+m))),  B = (l+m-1)/(l-m)*sqrt(r2), B=0 at l=m+1
// Pbar(m,m) = D2(m)*sx^2*Pbar(m-2,m-2)
__global__ void init_tables() {
    int idx = threadIdx.x;
    if (idx < NK) {
        int l = 0;
        while ((l + 1) * (l + 2) / 2 <= idx) ++l;
        int m = idx - l * (l + 1) / 2;
        double A = 0.0, Bc = 0.0;
        if (l >= m + 1) {
            A = sqrt((double)((2 * l + 1) * (2 * l - 1)) /
                     (double)((l - m) * (l + m)));
            if (l >= m + 2) {
                double r = (double)(2 * l + 1) / (double)(2 * l - 3)
                         * (double)((l - m) * (l - m - 1))
                         / (double)((l + m) * (l + m - 1));
                Bc = (double)(l + m - 1) / (double)(l - m) * sqrt(r);
            }
        }
        g_AB[idx] = make_float2((float)A, (float)Bc);
    }
    if (idx >= 2 && idx < LMAX) {
        int m = idx;
        double r = (double)(2 * m + 1) / (double)(2 * m - 3);
        r /= (double)(2 * m) * (2 * m - 1) * (2 * m - 2) * (2 * m - 3);
        g_D2[m] = (float)((double)((2 * m - 1) * (2 * m - 3)) * sqrt(r));
    }
    if (idx == 0) {
        g_S[0] = (float)sqrt(1.0 / (4.0 * 3.14159265358979323846));
        g_S[1] = (float)(-sqrt(3.0 / (8.0 * 3.14159265358979323846)));
    }
}

// Rows l in [L0,L1); this thread handles m = PAR, PAR+2, ... Emits cols - CBASE.
template<int L0, int L1, int CBASE, int PAR>
__device__ __forceinline__ void compute_rows(
    float* __restrict__ row, const float2* __restrict__ sAB,
    const float* __restrict__ sD2,
    float x, float sx2, float seed,
    const float (&CM)[NM], const float (&SM)[NM],
    float (&Pa)[NM], float (&Pb)[NM])
{
    #pragma unroll
    for (int l = L0; l < L1; ++l) {
        float Pn[NM];
        #pragma unroll
        for (int j = 0; j < NM; ++j) {
            const int m = PAR + 2 * j;
            if (m > l) continue;
            if (m == l) {
                Pn[j] = (j == 0) ? seed : sD2[l] * sx2 * Pb[j - 1];
            } else {
                float2 ab = sAB[l * (l + 1) / 2 + m];   // LDS.64 broadcast
                Pn[j] = fmaf(ab.x * x, Pa[j], -(ab.y * Pb[j]));
            }
        }
        const int base = l * l + l - CBASE;
        #pragma unroll
        for (int j = 0; j < NM; ++j) {
            const int m = PAR + 2 * j;
            if (m > l) continue;
            float t = Pn[j];
            if (m == 0) row[base] = t;
            else { row[base + m] = t * CM[j]; row[base - m] = t * SM[j]; }
        }
        #pragma unroll
        for (int j = 0; j < NM; ++j) {
            const int m = PAR + 2 * j;
            if (m > l) continue;
            Pb[j] = Pa[j]; Pa[j] = Pn[j];
        }
    }
}

// Coalesced, conflict-free scalar copy: col fastest -> 32 lanes read 32
// consecutive floats of one smem row (stride 101 => 32 distinct banks) and
// store one contiguous 128B gmem line.
template<int CBASE, int COLS>
__device__ __forceinline__ void writeback(
    const float* __restrict__ sh, float* __restrict__ out,
    int p0, int np, int tid)
{
    int total = np * COLS;
    for (int j = tid; j < total; j += T) {
        int r = j / COLS;            // constexpr divisor -> mul/shift
        int k = j - r * COLS;
        out[(size_t)(p0 + r) * NCOL + CBASE + k] = sh[r * STRIDE + k];
    }
}

__global__ __launch_bounds__(T, 3) void sh_kernel(
    const float* __restrict__ lonlat, float* __restrict__ out, int B)
{
    __shared__ float2 sAB[NK];
    __shared__ float  sD2[LMAX];
    __shared__ float  sS[2];
    extern __shared__ float sh[];

    const int tid = threadIdx.x;
    const int pt  = tid & (PTS - 1);
    const int par = tid >> 7;               // 0: even m, 1: odd m
    const int p0  = blockIdx.x * PTS;
    const int np  = min(PTS, B - p0);

    for (int i = tid; i < NK; i += T) sAB[i] = g_AB[i];
    if (tid < LMAX) sD2[tid] = g_D2[tid];
    if (tid < 2)    sS[tid]  = g_S[tid];
    __syncthreads();

    const bool active = (pt < np);
    float x = 0.f, sx2 = 0.f, seed = 0.f;
    float CM[NM], SM[NM], Pa[NM], Pb[NM];

    if (active) {
        float2 ll = reinterpret_cast<const float2*>(lonlat)[p0 + pt];
        const float d2r = 0.017453292519943295f;
        float phi   = (ll.x + 180.0f) * d2r;
        float theta = (ll.y +  90.0f) * d2r;
        x = cosf(theta);
        float sx = sinf(theta);
        sx2 = sx * sx;
        float s1, c1;
        sincosf(phi, &s1, &c1);
        float c2 = c1 * c1 - s1 * s1;       // cos(2phi)
        float s2 = 2.0f * s1 * c1;          // sin(2phi)
        const float SQ2 = 1.41421356237309505f;
        if (par == 0) { CM[0] = SQ2;      SM[0] = 0.0f;
                        seed = sS[0]; }
        else          { CM[0] = SQ2 * c1; SM[0] = SQ2 * s1;
                        seed = sS[1] * sx; }
        #pragma unroll
        for (int j = 1; j < NM; ++j) {
            CM[j] = CM[j - 1] * c2 - SM[j - 1] * s2;
            SM[j] = SM[j - 1] * c2 + CM[j - 1] * s2;
        }
        #pragma unroll
        for (int j = 0; j < NM; ++j) { Pa[j] = 0.0f; Pb[j] = 0.0f; }
    }

    float* row = sh + pt * STRIDE;

    // chunk 0: l 0..9   cols [0,100)
    if (active) {
        if (par == 0) compute_rows<0, 10, 0, 0>(row, sAB, sD2, x, sx2, seed, CM, SM, Pa, Pb);
        else          compute_rows<0, 10, 0, 1>(row, sAB, sD2, x, sx2, seed, CM, SM, Pa, Pb);
    }
    __syncthreads();
    writeback<0, 100>(sh, out, p0, np, tid);
    __syncthreads();

    // chunk 1: l 10..13 cols [100,196)
    if (active) {
        if (par == 0) compute_rows<10, 14, 100, 0>(row, sAB, sD2, x, sx2, seed, CM, SM, Pa, Pb);
        else          compute_rows<10, 14, 100, 1>(row, sAB, sD2, x, sx2, seed, CM, SM, Pa, Pb);
    }
    __syncthreads();
    writeback<100, 96>(sh, out, p0, np, tid);
    __syncthreads();

    // chunk 2: l 14..15 cols [196,256)
    if (active) {
        if (par == 0) compute_rows<14, 16, 196, 0>(row, sAB, sD2, x, sx2, seed, CM, SM, Pa, Pb);
        else          compute_rows<14, 16, 196, 1>(row, sAB, sD2, x, sx2, seed, CM, SM, Pa, Pb);
    }
    __syncthreads();
    writeback<196, 60>(sh, out, p0, np, tid);
    __syncthreads();

    // chunk 3: l 16..17 cols [256,324)
    if (active) {
        if (par == 0) compute_rows<16, 18, 256, 0>(row, sAB, sD2, x, sx2, seed, CM, SM, Pa, Pb);
        else          compute_rows<16, 18, 256, 1>(row, sAB, sD2, x, sx2, seed, CM, SM, Pa, Pb);
    }
    __syncthreads();
    writeback<256, 68>(sh, out, p0, np, tid);
    __syncthreads();

    // chunk 4: l 18..19 cols [324,400)
    if (active) {
        if (par == 0) compute_rows<18, 20, 324, 0>(row, sAB, sD2, x, sx2, seed, CM, SM, Pa, Pb);
        else          compute_rows<18, 20, 324, 1>(row, sAB, sD2, x, sx2, seed, CM, SM, Pa, Pb);
    }
    __syncthreads();
    writeback<324, 76>(sh, out, p0, np, tid);
}

extern "C" void kernel_launch(void* const* d_in, const int* in_sizes, int n_in,
                              void* d_out, int out_size)
{
    const float* lonlat = (const float*)d_in[0];
    float* out = (float*)d_out;
    int B = in_sizes[0] / 2;

    size_t smem = (size_t)PTS * STRIDE * sizeof(float);   // 51,712 B dynamic
    cudaFuncSetAttribute(sh_kernel,
                         cudaFuncAttributeMaxDynamicSharedMemorySize, (int)smem);

    init_tables<<<1, 256>>>();
    int grid = (B + PTS - 1) / PTS;
    sh_kernel<<<grid, T, smem>>>(lonlat, out, B);
}

// round 8
// speedup vs baseline: 1.0098x; 1.0056x over previous
#include <cuda_runtime.h>
#include <math.h>

#define LMAX 20
#define NK   210           // LMAX*(LMAX+1)/2
#define NCOL 400
#define T    256           // threads/block
#define PTS  128           // points/block (2 threads per point)
#define STRIDE 101         // smem row stride in floats (odd -> conflict-free STS)
#define NM   10            // m values per parity-thread

__device__ float2 g_AB[NK];     // normalized recurrence coeffs A,B per (l,m)
__device__ float  g_D2[LMAX];   // skip-2 sectoral diagonal coeff per l
__device__ float  g_S[2];       // seeds: Pbar(0,0), and -norm(1,1) (x sx)

// Tables in double precision. Pbar(l,m) = K(l,m)*P(l,m) (Condon-Shortley in P).
// Pbar(l,m) = A(l,m)*x*Pbar(l-1,m) - B(l,m)*Pbar(l-2,m)
//   A = sqrt((2l-1)(2l+1)/((l-m)(l+m))),  B = (l+m-1)/(l-m)*sqrt(r2), B=0 at l=m+1
// Pbar(m,m) = D2(m)*sx^2*Pbar(m-2,m-2)
__global__ void init_tables() {
    int idx = threadIdx.x;
    if (idx < NK) {
        int l = 0;
        while ((l + 1) * (l + 2) / 2 <= idx) ++l;
        int m = idx - l * (l + 1) / 2;
        double A = 0.0, Bc = 0.0;
        if (l >= m + 1) {
            A = sqrt((double)((2 * l + 1) * (2 * l - 1)) /
                     (double)((l - m) * (l + m)));
            if (l >= m + 2) {
                double r = (double)(2 * l + 1) / (double)(2 * l - 3)
                         * (double)((l - m) * (l - m - 1))
                         / (double)((l + m) * (l + m - 1));
                Bc = (double)(l + m - 1) / (double)(l - m) * sqrt(r);
            }
        }
        g_AB[idx] = make_float2((float)A, (float)Bc);
    }
    if (idx >= 2 && idx < LMAX) {
        int m = idx;
        double r = (double)(2 * m + 1) / (double)(2 * m - 3);
        r /= (double)(2 * m) * (2 * m - 1) * (2 * m - 2) * (2 * m - 3);
        g_D2[m] = (float)((double)((2 * m - 1) * (2 * m - 3)) * sqrt(r));
    }
    if (idx == 0) {
        g_S[0] = (float)sqrt(1.0 / (4.0 * 3.14159265358979323846));
        g_S[1] = (float)(-sqrt(3.0 / (8.0 * 3.14159265358979323846)));
    }
}

// Rows l in [L0,L1); this thread handles m = PAR, PAR+2, ... Emits cols - CBASE.
template<int L0, int L1, int CBASE, int PAR>
__device__ __forceinline__ void compute_rows(
    float* __restrict__ row, const float2* __restrict__ sAB,
    const float* __restrict__ sD2,
    float x, float sx2, float seed,
    const float (&CM)[NM], const float (&SM)[NM],
    float (&Pa)[NM], float (&Pb)[NM])
{
    #pragma unroll
    for (int l = L0; l < L1; ++l) {
        float Pn[NM];
        #pragma unroll
        for (int j = 0; j < NM; ++j) {
            const int m = PAR + 2 * j;
            if (m > l) continue;
            if (m == l) {
                Pn[j] = (j == 0) ? seed : sD2[l] * sx2 * Pb[j - 1];
            } else {
                float2 ab = sAB[l * (l + 1) / 2 + m];   // LDS.64 broadcast
                Pn[j] = fmaf(ab.x * x, Pa[j], -(ab.y * Pb[j]));
            }
        }
        const int base = l * l + l - CBASE;
        #pragma unroll
        for (int j = 0; j < NM; ++j) {
            const int m = PAR + 2 * j;
            if (m > l) continue;
            float t = Pn[j];
            if (m == 0) row[base] = t;
            else { row[base + m] = t * CM[j]; row[base - m] = t * SM[j]; }
        }
        #pragma unroll
        for (int j = 0; j < NM; ++j) {
            const int m = PAR + 2 * j;
            if (m > l) continue;
            Pb[j] = Pa[j]; Pa[j] = Pn[j];
        }
    }
}

// Coalesced, conflict-free scalar copy: col fastest -> 32 lanes read 32
// consecutive floats of one smem row (stride 101 => 32 distinct banks) and
// store one contiguous 128B gmem line.
template<int CBASE, int COLS>
__device__ __forceinline__ void writeback(
    const float* __restrict__ sh, float* __restrict__ out,
    int p0, int np, int tid)
{
    int total = np * COLS;
    for (int j = tid; j < total; j += T) {
        int r = j / COLS;            // constexpr divisor -> mul/shift
        int k = j - r * COLS;
        out[(size_t)(p0 + r) * NCOL + CBASE + k] = sh[r * STRIDE + k];
    }
}

__global__ __launch_bounds__(T, 3) void sh_kernel(
    const float* __restrict__ lonlat, float* __restrict__ out, int B)
{
    __shared__ float2 sAB[NK];
    __shared__ float  sD2[LMAX];
    __shared__ float  sS[2];
    extern __shared__ float sh[];

    const int tid = threadIdx.x;
    const int pt  = tid & (PTS - 1);
    const int par = tid >> 7;               // 0: even m, 1: odd m
    const int p0  = blockIdx.x * PTS;
    const int np  = min(PTS, B - p0);

    for (int i = tid; i < NK; i += T) sAB[i] = g_AB[i];
    if (tid < LMAX) sD2[tid] = g_D2[tid];
    if (tid < 2)    sS[tid]  = g_S[tid];
    __syncthreads();

    const bool active = (pt < np);
    float x = 0.f, sx2 = 0.f, seed = 0.f;
    float CM[NM], SM[NM], Pa[NM], Pb[NM];

    if (active) {
        float2 ll = reinterpret_cast<const float2*>(lonlat)[p0 + pt];
        const float d2r = 0.017453292519943295f;
        float phi   = (ll.x + 180.0f) * d2r;
        float theta = (ll.y +  90.0f) * d2r;
        x = cosf(theta);
        float sx = sinf(theta);
        sx2 = sx * sx;
        float s1, c1;
        sincosf(phi, &s1, &c1);
        float c2 = c1 * c1 - s1 * s1;       // cos(2phi)
        float s2 = 2.0f * s1 * c1;          // sin(2phi)
        const float SQ2 = 1.41421356237309505f;
        if (par == 0) { CM[0] = SQ2;      SM[0] = 0.0f;
                        seed = sS[0]; }
        else          { CM[0] = SQ2 * c1; SM[0] = SQ2 * s1;
                        seed = sS[1] * sx; }
        #pragma unroll
        for (int j = 1; j < NM; ++j) {
            CM[j] = CM[j - 1] * c2 - SM[j - 1] * s2;
            SM[j] = SM[j - 1] * c2 + CM[j - 1] * s2;
        }
        #pragma unroll
        for (int j = 0; j < NM; ++j) { Pa[j] = 0.0f; Pb[j] = 0.0f; }
    }

    float* row = sh + pt * STRIDE;

    // chunk 0: l 0..9   cols [0,100)
    if (active) {
        if (par == 0) compute_rows<0, 10, 0, 0>(row, sAB, sD2, x, sx2, seed, CM, SM, Pa, Pb);
        else          compute_rows<0, 10, 0, 1>(row, sAB, sD2, x, sx2, seed, CM, SM, Pa, Pb);
    }
    __syncthreads();
    writeback<0, 100>(sh, out, p0, np, tid);
    __syncthreads();

    // chunk 1: l 10..13 cols [100,196)
    if (active) {
        if (par == 0) compute_rows<10, 14, 100, 0>(row, sAB, sD2, x, sx2, seed, CM, SM, Pa, Pb);
        else          compute_rows<10, 14, 100, 1>(row, sAB, sD2, x, sx2, seed, CM, SM, Pa, Pb);
    }
    __syncthreads();
    writeback<100, 96>(sh, out, p0, np, tid);
    __syncthreads();

    // chunk 2: l 14..15 cols [196,256)
    if (active) {
        if (par == 0) compute_rows<14, 16, 196, 0>(row, sAB, sD2, x, sx2, seed, CM, SM, Pa, Pb);
        else          compute_rows<14, 16, 196, 1>(row, sAB, sD2, x, sx2, seed, CM, SM, Pa, Pb);
    }
    __syncthreads();
    writeback<196, 60>(sh, out, p0, np, tid);
    __syncthreads();

    // chunk 3: l 16..17 cols [256,324)
    if (active) {
        if (par == 0) compute_rows<16, 18, 256, 0>(row, sAB, sD2, x, sx2, seed, CM, SM, Pa, Pb);
        else          compute_rows<16, 18, 256, 1>(row, sAB, sD2, x, sx2, seed, CM, SM, Pa, Pb);
    }
    __syncthreads();
    writeback<256, 68>(sh, out, p0, np, tid);
    __syncthreads();

    // chunk 4: l 18..19 cols [324,400)
    if (active) {
        if (par == 0) compute_rows<18, 20, 324, 0>(row, sAB, sD2, x, sx2, seed, CM, SM, Pa, Pb);
        else          compute_rows<18, 20, 324, 1>(row, sAB, sD2, x, sx2, seed, CM, SM, Pa, Pb);
    }
    __syncthreads();
    writeback<324, 76>(sh, out, p0, np, tid);
}

extern "C" void kernel_launch(void* const* d_in, const int* in_sizes, int n_in,
                              void* d_out, int out_size)
{
    const float* lonlat = (const float*)d_in[0];
    float* out = (float*)d_out;
    int B = in_sizes[0] / 2;

    size_t smem = (size_t)PTS * STRIDE * sizeof(float);   // 51,712 B dynamic
    cudaFuncSetAttribute(sh_kernel,
                         cudaFuncAttributeMaxDynamicSharedMemorySize, (int)smem);

    init_tables<<<1, 256>>>();
    int grid = (B + PTS - 1) / PTS;
    sh_kernel<<<grid, T, smem>>>(lonlat, out, B);
}

// round 9
// speedup vs baseline: 1.1689x; 1.1576x over previous
#include <cuda_runtime.h>
#include <math.h>

#define LMAX 20
#define NK   210           // LMAX*(LMAX+1)/2
#define NCOL 400
#define T    256           // threads/block
#define PTS  128           // points/block (2 threads per point)
#define STRIDE 101         // smem row stride in floats (odd -> conflict-free STS)
#define NM   10            // m values per parity-thread
#define NWARP (T / 32)

__device__ float2 g_AB[NK];     // normalized recurrence coeffs A,B per (l,m)
__device__ float  g_D2[LMAX];   // skip-2 sectoral diagonal coeff per l
__device__ float  g_S[2];       // seeds: Pbar(0,0), and -norm(1,1) (x sx)

// Tables in double precision. Pbar(l,m) = K(l,m)*P(l,m) (Condon-Shortley in P).
__global__ void init_tables() {
    int idx = threadIdx.x;
    if (idx < NK) {
        int l = 0;
        while ((l + 1) * (l + 2) / 2 <= idx) ++l;
        int m = idx - l * (l + 1) / 2;
        double A = 0.0, Bc = 0.0;
        if (l >= m + 1) {
            A = sqrt((double)((2 * l + 1) * (2 * l - 1)) /
                     (double)((l - m) * (l + m)));
            if (l >= m + 2) {
                double r = (double)(2 * l + 1) / (double)(2 * l - 3)
                         * (double)((l - m) * (l - m - 1))
                         / (double)((l + m) * (l + m - 1));
                Bc = (double)(l + m - 1) / (double)(l - m) * sqrt(r);
            }
        }
        g_AB[idx] = make_float2((float)A, (float)Bc);
    }
    if (idx >= 2 && idx < LMAX) {
        int m = idx;
        double r = (double)(2 * m + 1) / (double)(2 * m - 3);
        r /= (double)(2 * m) * (2 * m - 1) * (2 * m - 2) * (2 * m - 3);
        g_D2[m] = (float)((double)((2 * m - 1) * (2 * m - 3)) * sqrt(r));
    }
    if (idx == 0) {
        g_S[0] = (float)sqrt(1.0 / (4.0 * 3.14159265358979323846));
        g_S[1] = (float)(-sqrt(3.0 / (8.0 * 3.14159265358979323846)));
    }
}

// Rows l in [L0,L1); this thread handles m = PAR, PAR+2, ... Emits cols - CBASE.
template<int L0, int L1, int CBASE, int PAR>
__device__ __forceinline__ void compute_rows(
    float* __restrict__ row, const float2* __restrict__ sAB,
    const float* __restrict__ sD2,
    float x, float sx2, float seed,
    const float (&CM)[NM], const float (&SM)[NM],
    float (&Pa)[NM], float (&Pb)[NM])
{
    #pragma unroll
    for (int l = L0; l < L1; ++l) {
        float Pn[NM];
        #pragma unroll
        for (int j = 0; j < NM; ++j) {
            const int m = PAR + 2 * j;
            if (m > l) continue;
            if (m == l) {
                Pn[j] = (j == 0) ? seed : sD2[l] * sx2 * Pb[j - 1];
            } else {
                float2 ab = sAB[l * (l + 1) / 2 + m];   // LDS.64 broadcast
                Pn[j] = fmaf(ab.x * x, Pa[j], -(ab.y * Pb[j]));
            }
        }
        const int base = l * l + l - CBASE;
        #pragma unroll
        for (int j = 0; j < NM; ++j) {
            const int m = PAR + 2 * j;
            if (m > l) continue;
            float t = Pn[j];
            if (m == 0) row[base] = t;
            else { row[base + m] = t * CM[j]; row[base - m] = t * SM[j]; }
        }
        #pragma unroll
        for (int j = 0; j < NM; ++j) {
            const int m = PAR + 2 * j;
            if (m > l) continue;
            Pb[j] = Pa[j]; Pa[j] = Pn[j];
        }
    }
}

// Row-per-warp writeback: per row, lanes cover 32 consecutive cols per
// unrolled step (immediate offsets, conflict-free LDS, coalesced 128B STG).
// ~3 warp-instructions per 32 floats (vs ~9 for the div/mod form).
template<int CBASE, int COLS>
__device__ __forceinline__ void writeback(
    const float* __restrict__ sh, float* __restrict__ out,
    int p0, int np, int warp, int lane)
{
    constexpr int NFULL = COLS / 32;
    constexpr int REM   = COLS - NFULL * 32;
    for (int r = warp; r < np; r += NWARP) {
        const float* s = sh + r * STRIDE + lane;
        float* d = out + (size_t)(p0 + r) * NCOL + CBASE + lane;
        #pragma unroll
        for (int u = 0; u < NFULL; ++u)
            d[u * 32] = s[u * 32];
        if (REM && lane < REM)
            d[NFULL * 32] = s[NFULL * 32];
    }
}

__global__ __launch_bounds__(T, 3) void sh_kernel(
    const float* __restrict__ lonlat, float* __restrict__ out, int B)
{
    __shared__ float2 sAB[NK];
    __shared__ float  sD2[LMAX];
    __shared__ float  sS[2];
    extern __shared__ float sh[];

    const int tid  = threadIdx.x;
    const int lane = tid & 31;
    const int warp = tid >> 5;
    const int pt   = tid & (PTS - 1);
    const int par  = tid >> 7;               // 0: even m, 1: odd m
    const int p0   = blockIdx.x * PTS;
    const int np   = min(PTS, B - p0);

    for (int i = tid; i < NK; i += T) sAB[i] = g_AB[i];
    if (tid < LMAX) sD2[tid] = g_D2[tid];
    if (tid < 2)    sS[tid]  = g_S[tid];
    __syncthreads();

    const bool active = (pt < np);
    float x = 0.f, sx2 = 0.f, seed = 0.f;
    float CM[NM], SM[NM], Pa[NM], Pb[NM];

    if (active) {
        float2 ll = reinterpret_cast<const float2*>(lonlat)[p0 + pt];
        const float d2r = 0.017453292519943295f;
        float phi   = (ll.x + 180.0f) * d2r;
        float theta = (ll.y +  90.0f) * d2r;
        x = cosf(theta);
        float sx = sinf(theta);
        sx2 = sx * sx;
        float s1, c1;
        sincosf(phi, &s1, &c1);
        float c2 = c1 * c1 - s1 * s1;       // cos(2phi)
        float s2 = 2.0f * s1 * c1;          // sin(2phi)
        const float SQ2 = 1.41421356237309505f;
        if (par == 0) { CM[0] = SQ2;      SM[0] = 0.0f;
                        seed = sS[0]; }
        else          { CM[0] = SQ2 * c1; SM[0] = SQ2 * s1;
                        seed = sS[1] * sx; }
        #pragma unroll
        for (int j = 1; j < NM; ++j) {
            CM[j] = CM[j - 1] * c2 - SM[j - 1] * s2;
            SM[j] = SM[j - 1] * c2 + CM[j - 1] * s2;
        }
        #pragma unroll
        for (int j = 0; j < NM; ++j) { Pa[j] = 0.0f; Pb[j] = 0.0f; }
    }

    float* row = sh + pt * STRIDE;

    // chunk 0: l 0..9   cols [0,100)
    if (active) {
        if (par == 0) compute_rows<0, 10, 0, 0>(row, sAB, sD2, x, sx2, seed, CM, SM, Pa, Pb);
        else          compute_rows<0, 10, 0, 1>(row, sAB, sD2, x, sx2, seed, CM, SM, Pa, Pb);
    }
    __syncthreads();
    writeback<0, 100>(sh, out, p0, np, warp, lane);
    __syncthreads();

    // chunk 1: l 10..13 cols [100,196)
    if (active) {
        if (par == 0) compute_rows<10, 14, 100, 0>(row, sAB, sD2, x, sx2, seed, CM, SM, Pa, Pb);
        else          compute_rows<10, 14, 100, 1>(row, sAB, sD2, x, sx2, seed, CM, SM, Pa, Pb);
    }
    __syncthreads();
    writeback<100, 96>(sh, out, p0, np, warp, lane);
    __syncthreads();

    // chunk 2: l 14..15 cols [196,256)
    if (active) {
        if (par == 0) compute_rows<14, 16, 196, 0>(row, sAB, sD2, x, sx2, seed, CM, SM, Pa, Pb);
        else          compute_rows<14, 16, 196, 1>(row, sAB, sD2, x, sx2, seed, CM, SM, Pa, Pb);
    }
    __syncthreads();
    writeback<196, 60>(sh, out, p0, np, warp, lane);
    __syncthreads();

    // chunk 3: l 16..17 cols [256,324)
    if (active) {
        if (par == 0) compute_rows<16, 18, 256, 0>(row, sAB, sD2, x, sx2, seed, CM, SM, Pa, Pb);
        else          compute_rows<16, 18, 256, 1>(row, sAB, sD2, x, sx2, seed, CM, SM, Pa, Pb);
    }
    __syncthreads();
    writeback<256, 68>(sh, out, p0, np, warp, lane);
    __syncthreads();

    // chunk 4: l 18..19 cols [324,400)
    if (active) {
        if (par == 0) compute_rows<18, 20, 324, 0>(row, sAB, sD2, x, sx2, seed, CM, SM, Pa, Pb);
        else          compute_rows<18, 20, 324, 1>(row, sAB, sD2, x, sx2, seed, CM, SM, Pa, Pb);
    }
    __syncthreads();
    writeback<324, 76>(sh, out, p0, np, warp, lane);
}

extern "C" void kernel_launch(void* const* d_in, const int* in_sizes, int n_in,
                              void* d_out, int out_size)
{
    const float* lonlat = (const float*)d_in[0];
    float* out = (float*)d_out;
    int B = in_sizes[0] / 2;

    size_t smem = (size_t)PTS * STRIDE * sizeof(float);   // 51,712 B dynamic
    cudaFuncSetAttribute(sh_kernel,
                         cudaFuncAttributeMaxDynamicSharedMemorySize, (int)smem);

    init_tables<<<1, 256>>>();
    int grid = (B + PTS - 1) / PTS;
    sh_kernel<<<grid, T, smem>>>(lonlat, out, B);
}